// round 1
// baseline (speedup 1.0000x reference)
#include <cuda_runtime.h>
#include <cuda_bf16.h>
#include <math.h>

// ---------------- problem constants ----------------
#define BATCH   8
#define HIMG    56
#define WIMG    56
#define CDIM    384
#define NHEADS  12
#define HDIM    32
#define WIN     7
#define NTOK    49            // WIN*WIN
#define SHIFT_S 3
#define NWSIDE  8             // 56/7
#define WINS_PER_B 64
#define TOTWIN  512           // BATCH*64
#define MTOK    25088         // BATCH*56*56
#define FFNDIM  1536

// ---------------- scratch (device globals; allocation-free) ----------------
__device__ float g_xw [MTOK * CDIM];   // LN1'd, window-permuted tokens
__device__ float g_q  [MTOK * CDIM];
__device__ float g_k  [MTOK * CDIM];
__device__ float g_v  [MTOK * CDIM];
__device__ float g_ctx[MTOK * CDIM];   // attention context (windowed order)
__device__ float g_h  [MTOK * CDIM];   // shortcut + attn_out (token order)
__device__ float g_ln2[MTOK * CDIM];
__device__ float g_y1 [MTOK * FFNDIM]; // gelu(fc1)

// windowed row r  <->  original token t   (same map both directions: roll by
// -s then window-partition forward == window-reverse then roll +s backward)
__device__ __forceinline__ int win_row_to_token(int r) {
    int b    = r / (HIMG * WIMG);
    int rem  = r - b * (HIMG * WIMG);
    int widx = rem / NTOK;
    int tok  = rem - widx * NTOK;
    int wi = widx >> 3, wj = widx & 7;
    int i = tok / WIN, j = tok - i * WIN;
    int sh = wi * WIN + i + SHIFT_S; if (sh >= HIMG) sh -= HIMG;
    int sw = wj * WIN + j + SHIFT_S; if (sw >= WIMG) sw -= WIMG;
    return b * (HIMG * WIMG) + sh * WIMG + sw;
}

// ---------------- LayerNorm (one block per row, 128 threads x 3 elems) ------
// permute=1: out[r] = LN(x[token(r)])  (LN1 + window gather)
// permute=0: out[r] = LN(x[r])         (LN2)
__global__ void __launch_bounds__(128) ln_kernel(
    const float* __restrict__ x, const float* __restrict__ g,
    const float* __restrict__ b, float* __restrict__ out, int permute)
{
    int r = blockIdx.x;
    int t = permute ? win_row_to_token(r) : r;
    const float* xi = x + (size_t)t * CDIM;
    float*       yo = out + (size_t)r * CDIM;
    int tid = threadIdx.x;

    float v[3];
    float s = 0.f, ss = 0.f;
#pragma unroll
    for (int i = 0; i < 3; i++) {
        v[i] = xi[tid + i * 128];
        s += v[i]; ss += v[i] * v[i];
    }
#pragma unroll
    for (int o = 16; o; o >>= 1) {
        s  += __shfl_xor_sync(0xffffffffu, s,  o);
        ss += __shfl_xor_sync(0xffffffffu, ss, o);
    }
    __shared__ float red[8];
    __shared__ float stat[2];
    int wid = tid >> 5, lane = tid & 31;
    if (lane == 0) { red[wid] = s; red[4 + wid] = ss; }
    __syncthreads();
    if (tid == 0) {
        float S = red[0] + red[1] + red[2] + red[3];
        float SS = red[4] + red[5] + red[6] + red[7];
        float mu = S * (1.0f / CDIM);
        float var = SS * (1.0f / CDIM) - mu * mu;
        stat[0] = mu;
        stat[1] = rsqrtf(var + 1e-5f);
    }
    __syncthreads();
    float mu = stat[0], rstd = stat[1];
#pragma unroll
    for (int i = 0; i < 3; i++) {
        int c = tid + i * 128;
        yo[c] = (v[i] - mu) * rstd * g[c] + b[c];
    }
}

// ---------------- GEMM: C = A[M,K] @ B[K,N] + bias, fused epilogues --------
// EPI 0: store               C[r,n] = acc+bias
// EPI 1: exact GELU          C[r,n] = gelu(acc+bias)
// EPI 2: window-scatter+res  C[t,n] = add[t,n] + acc+bias  (t = token(r))
// EPI 3: residual            C[r,n] = add[r,n] + acc+bias
#define BM 64
#define BN 64
#define BK 16

template <int EPI>
__global__ void __launch_bounds__(256) gemm_kernel(
    const float* __restrict__ A, const float* __restrict__ B,
    const float* __restrict__ bias, const float* __restrict__ add,
    float* __restrict__ C, int M, int N, int K)
{
    __shared__ __align__(16) float As[BK][BM];
    __shared__ __align__(16) float Bs[BK][BN];

    int tid = threadIdx.x;
    int tx = tid & 15, ty = tid >> 4;
    int m0 = blockIdx.y * BM, n0 = blockIdx.x * BN;

    int arow = tid >> 2;               // 0..63
    int acol = (tid & 3) * 4;          // 0..12
    int brow = tid >> 4;               // 0..15
    int bcol = (tid & 15) * 4;         // 0..60

    const float* Aptr = A + (size_t)(m0 + arow) * K + acol;
    const float* Bptr = B + (size_t)brow * N + (n0 + bcol);

    float acc[4][4] = {};

    for (int k0 = 0; k0 < K; k0 += BK) {
        float4 a4 = *(const float4*)(Aptr + k0);
        float4 b4 = *(const float4*)(Bptr + (size_t)k0 * N);
        As[acol + 0][arow] = a4.x;
        As[acol + 1][arow] = a4.y;
        As[acol + 2][arow] = a4.z;
        As[acol + 3][arow] = a4.w;
        *(float4*)&Bs[brow][bcol] = b4;
        __syncthreads();
#pragma unroll
        for (int k = 0; k < BK; k++) {
            float4 av = *(const float4*)&As[k][ty * 4];
            float4 bv = *(const float4*)&Bs[k][tx * 4];
            acc[0][0] += av.x * bv.x; acc[0][1] += av.x * bv.y;
            acc[0][2] += av.x * bv.z; acc[0][3] += av.x * bv.w;
            acc[1][0] += av.y * bv.x; acc[1][1] += av.y * bv.y;
            acc[1][2] += av.y * bv.z; acc[1][3] += av.y * bv.w;
            acc[2][0] += av.z * bv.x; acc[2][1] += av.z * bv.y;
            acc[2][2] += av.z * bv.z; acc[2][3] += av.z * bv.w;
            acc[3][0] += av.w * bv.x; acc[3][1] += av.w * bv.y;
            acc[3][2] += av.w * bv.z; acc[3][3] += av.w * bv.w;
        }
        __syncthreads();
    }

#pragma unroll
    for (int i = 0; i < 4; i++) {
        int r = m0 + ty * 4 + i;
        int orow = (EPI == 2) ? win_row_to_token(r) : r;
#pragma unroll
        for (int j = 0; j < 4; j++) {
            int n = n0 + tx * 4 + j;
            float val = acc[i][j] + bias[n];
            if (EPI == 1) {
                val = 0.5f * val * (1.0f + erff(val * 0.7071067811865475f));
            } else if (EPI == 2 || EPI == 3) {
                val += add[(size_t)orow * N + n];
            }
            C[(size_t)orow * N + n] = val;
        }
    }
}

// ---------------- fused window attention: one block per (window, head) -----
__global__ void __launch_bounds__(256) attn_kernel(
    const float* __restrict__ Q, const float* __restrict__ Kt,
    const float* __restrict__ V, const float* __restrict__ rpb,
    const int* __restrict__ rpi, float* __restrict__ O)
{
    int win = blockIdx.x;   // 0..511
    int h   = blockIdx.y;   // 0..11
    int tid = threadIdx.x;  // 256

    __shared__ float qs[NTOK][HDIM];
    __shared__ float ks[NTOK][HDIM];
    __shared__ float vs[NTOK][HDIM];
    __shared__ float sc[NTOK][NTOK + 1];
    __shared__ int   codes[NTOK];

    int widx = win & 63;
    int wi = widx >> 3, wj = widx & 7;
    if (tid < NTOK) {
        int i = tid / WIN, j = tid - i * WIN;
        int r = wi * WIN + i, c = wj * WIN + j;
        int rc = (r < HIMG - WIN) ? 0 : (r < HIMG - SHIFT_S ? 1 : 2);
        int cc = (c < WIMG - WIN) ? 0 : (c < WIMG - SHIFT_S ? 1 : 2);
        codes[tid] = rc * 3 + cc;
    }

    const size_t base = (size_t)win * NTOK * CDIM + h * HDIM;
    for (int idx = tid; idx < NTOK * HDIM; idx += 256) {
        int n = idx >> 5, d = idx & 31;
        size_t gi = base + (size_t)n * CDIM + d;
        qs[n][d] = Q[gi];
        ks[n][d] = Kt[gi];
        vs[n][d] = V[gi];
    }
    __syncthreads();

    const float scale = 0.17677669529663687f;  // 1/sqrt(32)
    for (int idx = tid; idx < NTOK * NTOK; idx += 256) {
        int n = idx / NTOK, m = idx - n * NTOK;
        float s = 0.f;
#pragma unroll
        for (int d = 0; d < HDIM; d++) s += qs[n][d] * ks[m][d];
        s = s * scale + rpb[rpi[idx] * NHEADS + h];
        if (codes[n] != codes[m]) s -= 100.0f;
        sc[n][m] = s;
    }
    __syncthreads();

    // softmax: one warp per row
    int wid = tid >> 5, lane = tid & 31;
    for (int n = wid; n < NTOK; n += 8) {
        float v0 = sc[n][lane];
        float v1 = (lane + 32 < NTOK) ? sc[n][lane + 32] : -1e30f;
        float mx = fmaxf(v0, v1);
#pragma unroll
        for (int o = 16; o; o >>= 1) mx = fmaxf(mx, __shfl_xor_sync(0xffffffffu, mx, o));
        float e0 = expf(v0 - mx);
        float e1 = (lane + 32 < NTOK) ? expf(v1 - mx) : 0.f;
        float sum = e0 + e1;
#pragma unroll
        for (int o = 16; o; o >>= 1) sum += __shfl_xor_sync(0xffffffffu, sum, o);
        float inv = 1.0f / sum;
        sc[n][lane] = e0 * inv;
        if (lane + 32 < NTOK) sc[n][lane + 32] = e1 * inv;
    }
    __syncthreads();

    for (int idx = tid; idx < NTOK * HDIM; idx += 256) {
        int n = idx >> 5, d = idx & 31;
        float s = 0.f;
#pragma unroll
        for (int m = 0; m < NTOK; m++) s += sc[n][m] * vs[m][d];
        O[base + (size_t)n * CDIM + d] = s;
    }
}

// ---------------- launch ----------------------------------------------------
extern "C" void kernel_launch(void* const* d_in, const int* in_sizes, int n_in,
                              void* d_out, int out_size)
{
    const float* hidden  = (const float*)d_in[0];
    const float* ln1_g   = (const float*)d_in[1];
    const float* ln1_b   = (const float*)d_in[2];
    const float* q_w     = (const float*)d_in[3];
    const float* q_b     = (const float*)d_in[4];
    const float* k_w     = (const float*)d_in[5];
    const float* k_b     = (const float*)d_in[6];
    const float* v_w     = (const float*)d_in[7];
    const float* v_b     = (const float*)d_in[8];
    const float* rpb     = (const float*)d_in[9];
    const int*   rpi     = (const int*)  d_in[10];
    const float* proj_w  = (const float*)d_in[11];
    const float* proj_b  = (const float*)d_in[12];
    const float* ln2_g   = (const float*)d_in[13];
    const float* ln2_b   = (const float*)d_in[14];
    const float* fc1_w   = (const float*)d_in[15];
    const float* fc1_b   = (const float*)d_in[16];
    const float* fc2_w   = (const float*)d_in[17];
    const float* fc2_b   = (const float*)d_in[18];
    float* out = (float*)d_out;

    float *p_xw, *p_q, *p_k, *p_v, *p_ctx, *p_h, *p_ln2, *p_y1;
    cudaGetSymbolAddress((void**)&p_xw,  g_xw);
    cudaGetSymbolAddress((void**)&p_q,   g_q);
    cudaGetSymbolAddress((void**)&p_k,   g_k);
    cudaGetSymbolAddress((void**)&p_v,   g_v);
    cudaGetSymbolAddress((void**)&p_ctx, g_ctx);
    cudaGetSymbolAddress((void**)&p_h,   g_h);
    cudaGetSymbolAddress((void**)&p_ln2, g_ln2);
    cudaGetSymbolAddress((void**)&p_y1,  g_y1);

    // 1) LN1 + shift-roll + window partition (gather)
    ln_kernel<<<MTOK, 128>>>(hidden, ln1_g, ln1_b, p_xw, 1);

    // 2) QKV projections
    dim3 gq(CDIM / BN, MTOK / BM);
    gemm_kernel<0><<<gq, 256>>>(p_xw, q_w, q_b, nullptr, p_q, MTOK, CDIM, CDIM);
    gemm_kernel<0><<<gq, 256>>>(p_xw, k_w, k_b, nullptr, p_k, MTOK, CDIM, CDIM);
    gemm_kernel<0><<<gq, 256>>>(p_xw, v_w, v_b, nullptr, p_v, MTOK, CDIM, CDIM);

    // 3) windowed attention (scores + rpb + shift mask + softmax + ctx)
    attn_kernel<<<dim3(TOTWIN, NHEADS), 256>>>(p_q, p_k, p_v, rpb, rpi, p_ctx);

    // 4) output projection + window-reverse + roll-back + residual (scatter)
    gemm_kernel<2><<<gq, 256>>>(p_ctx, proj_w, proj_b, hidden, p_h, MTOK, CDIM, CDIM);

    // 5) LN2
    ln_kernel<<<MTOK, 128>>>(p_h, ln2_g, ln2_b, p_ln2, 0);

    // 6) fc1 + exact GELU
    gemm_kernel<1><<<dim3(FFNDIM / BN, MTOK / BM), 256>>>(
        p_ln2, fc1_w, fc1_b, nullptr, p_y1, MTOK, FFNDIM, CDIM);

    // 7) fc2 + residual -> final output
    gemm_kernel<3><<<gq, 256>>>(p_y1, fc2_w, fc2_b, p_h, out, MTOK, CDIM, FFNDIM);
}

// round 2
// speedup vs baseline: 3.1577x; 3.1577x over previous
#include <cuda_runtime.h>
#include <cuda_bf16.h>
#include <math.h>
#include <stdint.h>

// ---------------- problem constants ----------------
#define BATCH   8
#define HIMG    56
#define WIMG    56
#define CDIM    384
#define NHEADS  12
#define HDIM    32
#define WIN     7
#define NTOK    49
#define SHIFT_S 3
#define TOTWIN  512
#define MTOK    25088
#define FFNDIM  1536

typedef __nv_bfloat16 bf16;

// ---------------- scratch (device globals; allocation-free) ----------------
__device__ bf16  g_xw [MTOK * CDIM];
__device__ bf16  g_q  [MTOK * CDIM];
__device__ bf16  g_k  [MTOK * CDIM];
__device__ bf16  g_v  [MTOK * CDIM];
__device__ bf16  g_ctx[MTOK * CDIM];
__device__ float g_h  [MTOK * CDIM];
__device__ bf16  g_ln2[MTOK * CDIM];
__device__ bf16  g_y1 [MTOK * FFNDIM];
__device__ bf16  g_wq [CDIM * CDIM];
__device__ bf16  g_wk [CDIM * CDIM];
__device__ bf16  g_wv [CDIM * CDIM];
__device__ bf16  g_wp [CDIM * CDIM];
__device__ bf16  g_w1 [CDIM * FFNDIM];
__device__ bf16  g_w2 [FFNDIM * CDIM];

// windowed row r <-> original token t (same map both directions)
__device__ __forceinline__ int win_row_to_token(int r) {
    int b    = r / (HIMG * WIMG);
    int rem  = r - b * (HIMG * WIMG);
    int widx = rem / NTOK;
    int tok  = rem - widx * NTOK;
    int wi = widx >> 3, wj = widx & 7;
    int i = tok / WIN, j = tok - i * WIN;
    int sh = wi * WIN + i + SHIFT_S; if (sh >= HIMG) sh -= HIMG;
    int sw = wj * WIN + j + SHIFT_S; if (sw >= WIMG) sw -= WIMG;
    return b * (HIMG * WIMG) + sh * WIMG + sw;
}

// ---------------- fp32 -> bf16 convert ----------------
__global__ void __launch_bounds__(256) f2bf_kernel(
    const float* __restrict__ src, bf16* __restrict__ dst, int n4)
{
    int i = blockIdx.x * blockDim.x + threadIdx.x;
    if (i < n4) {
        float4 v = ((const float4*)src)[i];
        bf16 o[4] = {__float2bfloat16(v.x), __float2bfloat16(v.y),
                     __float2bfloat16(v.z), __float2bfloat16(v.w)};
        *(uint64_t*)(dst + i * 4) = *(uint64_t*)o;
    }
}

// ---------------- LayerNorm (fp32 in, bf16 out) ----------------
__global__ void __launch_bounds__(128) ln_kernel(
    const float* __restrict__ x, const float* __restrict__ g,
    const float* __restrict__ b, bf16* __restrict__ out, int permute)
{
    int r = blockIdx.x;
    int t = permute ? win_row_to_token(r) : r;
    const float* xi = x + (size_t)t * CDIM;
    bf16*        yo = out + (size_t)r * CDIM;
    int tid = threadIdx.x;

    float v[3];
    float s = 0.f, ss = 0.f;
#pragma unroll
    for (int i = 0; i < 3; i++) {
        v[i] = xi[tid + i * 128];
        s += v[i]; ss += v[i] * v[i];
    }
#pragma unroll
    for (int o = 16; o; o >>= 1) {
        s  += __shfl_xor_sync(0xffffffffu, s,  o);
        ss += __shfl_xor_sync(0xffffffffu, ss, o);
    }
    __shared__ float red[8];
    __shared__ float stat[2];
    int wid = tid >> 5, lane = tid & 31;
    if (lane == 0) { red[wid] = s; red[4 + wid] = ss; }
    __syncthreads();
    if (tid == 0) {
        float S  = red[0] + red[1] + red[2] + red[3];
        float SS = red[4] + red[5] + red[6] + red[7];
        float mu = S * (1.0f / CDIM);
        float var = SS * (1.0f / CDIM) - mu * mu;
        stat[0] = mu;
        stat[1] = rsqrtf(var + 1e-5f);
    }
    __syncthreads();
    float mu = stat[0], rstd = stat[1];
#pragma unroll
    for (int i = 0; i < 3; i++) {
        int c = tid + i * 128;
        yo[c] = __float2bfloat16((v[i] - mu) * rstd * g[c] + b[c]);
    }
}

// ---------------- HMMA bf16 GEMM ----------------
// C = A[M,K] @ B[K,N] + bias, epilogues:
//  0: store            1: exact GELU
//  2: scatter+residual (row permute, fp32 add)     3: residual (fp32 add)
#define GBM 128
#define GBN 64
#define GBK 32
#define ASTR 40
#define BSTR 72

#define CP16(dst, src) \
    asm volatile("cp.async.ca.shared.global [%0], [%1], 16;\n" :: \
        "r"((uint32_t)__cvta_generic_to_shared(dst)), "l"(src))
#define CP_COMMIT()  asm volatile("cp.async.commit_group;\n" ::)
#define CP_WAIT(n)   asm volatile("cp.async.wait_group %0;\n" :: "n"(n))

__device__ __forceinline__ void ldm_x4(uint32_t* r, const void* p) {
    uint32_t a = (uint32_t)__cvta_generic_to_shared(p);
    asm volatile("ldmatrix.sync.aligned.m8n8.x4.shared.b16 {%0,%1,%2,%3},[%4];"
        : "=r"(r[0]), "=r"(r[1]), "=r"(r[2]), "=r"(r[3]) : "r"(a));
}
__device__ __forceinline__ void ldm_x4t(uint32_t* r, const void* p) {
    uint32_t a = (uint32_t)__cvta_generic_to_shared(p);
    asm volatile("ldmatrix.sync.aligned.m8n8.x4.trans.shared.b16 {%0,%1,%2,%3},[%4];"
        : "=r"(r[0]), "=r"(r[1]), "=r"(r[2]), "=r"(r[3]) : "r"(a));
}
#define MMA16816(d, a, b0, b1) \
    asm volatile("mma.sync.aligned.m16n8k16.row.col.f32.bf16.bf16.f32 " \
        "{%0,%1,%2,%3},{%4,%5,%6,%7},{%8,%9},{%0,%1,%2,%3};" \
        : "+f"(d[0]), "+f"(d[1]), "+f"(d[2]), "+f"(d[3]) \
        : "r"(a[0]), "r"(a[1]), "r"(a[2]), "r"(a[3]), "r"(b0), "r"(b1))

template <int EPI, typename OutT>
__global__ void __launch_bounds__(256) mma_gemm(
    const bf16* __restrict__ A, const bf16* __restrict__ B,
    const float* __restrict__ bias, const float* __restrict__ add,
    OutT* __restrict__ C, int M, int N, int K)
{
    __shared__ __align__(16) bf16 As[2][GBM][ASTR];
    __shared__ __align__(16) bf16 Bs[2][GBK][BSTR];

    int t = threadIdx.x;
    int m0 = blockIdx.y * GBM, n0 = blockIdx.x * GBN;

    int ar = t >> 2, aseg = (t & 3) * 8;
    int br = t >> 3, bseg = (t & 7) * 8;
    const bf16* Ag = A + (size_t)(m0 + ar) * K + aseg;
    const bf16* Bg = B + (size_t)br * N + n0 + bseg;

    int lane = t & 31, w = t >> 5;
    int m0w = (w >> 1) * 32, nb = (w & 1) * 32;
    int lrow = (lane & 7) + (lane & 8);      // ldmatrix row offset
    int lcol = (lane & 16) >> 1;             // ldmatrix col offset

    float acc[2][4][4] = {};

    int nk = K / GBK;
    // prologue: tile 0
    {
        CP16(&As[0][ar][aseg], Ag);
        CP16(&As[0][ar + 64][aseg], Ag + (size_t)64 * K);
        CP16(&Bs[0][br][bseg], Bg);
        CP_COMMIT();
    }

    int buf = 0;
    for (int i = 0; i < nk; i++) {
        if (i + 1 < nk) {
            int k0 = (i + 1) * GBK;
            CP16(&As[buf ^ 1][ar][aseg], Ag + k0);
            CP16(&As[buf ^ 1][ar + 64][aseg], Ag + (size_t)64 * K + k0);
            CP16(&Bs[buf ^ 1][br][bseg], Bg + (size_t)k0 * N);
            CP_COMMIT();
            CP_WAIT(1);
        } else {
            CP_WAIT(0);
        }
        __syncthreads();

#pragma unroll
        for (int kk = 0; kk < GBK; kk += 16) {
            uint32_t a[2][4], b[2][4];
#pragma unroll
            for (int mi = 0; mi < 2; mi++)
                ldm_x4(a[mi], &As[buf][m0w + mi * 16 + lrow][kk + lcol]);
#pragma unroll
            for (int nj = 0; nj < 2; nj++)
                ldm_x4t(b[nj], &Bs[buf][kk + lrow][nb + nj * 16 + lcol]);
#pragma unroll
            for (int mi = 0; mi < 2; mi++) {
#pragma unroll
                for (int nt = 0; nt < 4; nt++)
                    MMA16816(acc[mi][nt], a[mi],
                             b[nt >> 1][(nt & 1) * 2], b[nt >> 1][(nt & 1) * 2 + 1]);
            }
        }
        __syncthreads();
        buf ^= 1;
    }

    // epilogue
#pragma unroll
    for (int mi = 0; mi < 2; mi++) {
        int rbase = m0 + m0w + mi * 16 + (lane >> 2);
#pragma unroll
        for (int h2 = 0; h2 < 2; h2++) {
            int row = rbase + 8 * h2;
            int orow = (EPI == 2) ? win_row_to_token(row) : row;
#pragma unroll
            for (int nt = 0; nt < 4; nt++) {
                int col = n0 + nb + nt * 8 + (lane & 3) * 2;
                float v0 = acc[mi][nt][2 * h2 + 0] + bias[col];
                float v1 = acc[mi][nt][2 * h2 + 1] + bias[col + 1];
                if (EPI == 1) {
                    v0 = 0.5f * v0 * (1.0f + erff(v0 * 0.7071067811865475f));
                    v1 = 0.5f * v1 * (1.0f + erff(v1 * 0.7071067811865475f));
                } else if (EPI == 2 || EPI == 3) {
                    const float* ap = add + (size_t)orow * N + col;
                    v0 += ap[0];
                    v1 += ap[1];
                }
                OutT* cp = C + (size_t)orow * N + col;
                if (sizeof(OutT) == 2) {
                    __nv_bfloat162 pk;
                    pk.x = __float2bfloat16(v0);
                    pk.y = __float2bfloat16(v1);
                    *(__nv_bfloat162*)cp = pk;
                } else {
                    float2 pk = make_float2(v0, v1);
                    *(float2*)cp = pk;
                }
            }
        }
    }
}

// ---------------- fused window attention ----------------
__global__ void __launch_bounds__(256) attn_kernel(
    const bf16* __restrict__ Q, const bf16* __restrict__ Kt,
    const bf16* __restrict__ V, const float* __restrict__ rpb,
    const int* __restrict__ rpi, bf16* __restrict__ O)
{
    int win = blockIdx.x;
    int h   = blockIdx.y;
    int tid = threadIdx.x;

    __shared__ float qs[NTOK][HDIM];
    __shared__ float ks[NTOK][HDIM];
    __shared__ float vs[NTOK][HDIM];
    __shared__ float sc[NTOK][NTOK + 1];
    __shared__ int   codes[NTOK];

    int widx = win & 63;
    int wi = widx >> 3, wj = widx & 7;
    if (tid < NTOK) {
        int i = tid / WIN, j = tid - i * WIN;
        int r = wi * WIN + i, c = wj * WIN + j;
        int rc = (r < HIMG - WIN) ? 0 : (r < HIMG - SHIFT_S ? 1 : 2);
        int cc = (c < WIMG - WIN) ? 0 : (c < WIMG - SHIFT_S ? 1 : 2);
        codes[tid] = rc * 3 + cc;
    }

    const size_t base = (size_t)win * NTOK * CDIM + h * HDIM;
    for (int idx = tid; idx < NTOK * HDIM; idx += 256) {
        int n = idx >> 5, d = idx & 31;
        size_t gi = base + (size_t)n * CDIM + d;
        qs[n][d] = __bfloat162float(Q[gi]);
        ks[n][d] = __bfloat162float(Kt[gi]);
        vs[n][d] = __bfloat162float(V[gi]);
    }
    __syncthreads();

    const float scale = 0.17677669529663687f;  // 1/sqrt(32)
    for (int idx = tid; idx < NTOK * NTOK; idx += 256) {
        int n = idx / NTOK, m = idx - n * NTOK;
        float s = 0.f;
#pragma unroll
        for (int d = 0; d < HDIM; d++) s += qs[n][d] * ks[m][d];
        s = s * scale + rpb[rpi[idx] * NHEADS + h];
        if (codes[n] != codes[m]) s -= 100.0f;
        sc[n][m] = s;
    }
    __syncthreads();

    int wid = tid >> 5, lane = tid & 31;
    for (int n = wid; n < NTOK; n += 8) {
        float v0 = sc[n][lane];
        float v1 = (lane + 32 < NTOK) ? sc[n][lane + 32] : -1e30f;
        float mx = fmaxf(v0, v1);
#pragma unroll
        for (int o = 16; o; o >>= 1) mx = fmaxf(mx, __shfl_xor_sync(0xffffffffu, mx, o));
        float e0 = expf(v0 - mx);
        float e1 = (lane + 32 < NTOK) ? expf(v1 - mx) : 0.f;
        float sum = e0 + e1;
#pragma unroll
        for (int o = 16; o; o >>= 1) sum += __shfl_xor_sync(0xffffffffu, sum, o);
        float inv = 1.0f / sum;
        sc[n][lane] = e0 * inv;
        if (lane + 32 < NTOK) sc[n][lane + 32] = e1 * inv;
    }
    __syncthreads();

    for (int idx = tid; idx < NTOK * HDIM; idx += 256) {
        int n = idx >> 5, d = idx & 31;
        float s = 0.f;
#pragma unroll
        for (int m = 0; m < NTOK; m++) s += sc[n][m] * vs[m][d];
        O[base + (size_t)n * CDIM + d] = __float2bfloat16(s);
    }
}

// ---------------- launch ----------------
extern "C" void kernel_launch(void* const* d_in, const int* in_sizes, int n_in,
                              void* d_out, int out_size)
{
    const float* hidden  = (const float*)d_in[0];
    const float* ln1_g   = (const float*)d_in[1];
    const float* ln1_b   = (const float*)d_in[2];
    const float* q_w     = (const float*)d_in[3];
    const float* q_b     = (const float*)d_in[4];
    const float* k_w     = (const float*)d_in[5];
    const float* k_b     = (const float*)d_in[6];
    const float* v_w     = (const float*)d_in[7];
    const float* v_b     = (const float*)d_in[8];
    const float* rpb     = (const float*)d_in[9];
    const int*   rpi     = (const int*)  d_in[10];
    const float* proj_w  = (const float*)d_in[11];
    const float* proj_b  = (const float*)d_in[12];
    const float* ln2_g   = (const float*)d_in[13];
    const float* ln2_b   = (const float*)d_in[14];
    const float* fc1_w   = (const float*)d_in[15];
    const float* fc1_b   = (const float*)d_in[16];
    const float* fc2_w   = (const float*)d_in[17];
    const float* fc2_b   = (const float*)d_in[18];
    float* out = (float*)d_out;

    bf16 *p_xw, *p_q, *p_k, *p_v, *p_ctx, *p_ln2, *p_y1;
    bf16 *p_wq, *p_wk, *p_wv, *p_wp, *p_w1, *p_w2;
    float *p_h;
    cudaGetSymbolAddress((void**)&p_xw,  g_xw);
    cudaGetSymbolAddress((void**)&p_q,   g_q);
    cudaGetSymbolAddress((void**)&p_k,   g_k);
    cudaGetSymbolAddress((void**)&p_v,   g_v);
    cudaGetSymbolAddress((void**)&p_ctx, g_ctx);
    cudaGetSymbolAddress((void**)&p_h,   g_h);
    cudaGetSymbolAddress((void**)&p_ln2, g_ln2);
    cudaGetSymbolAddress((void**)&p_y1,  g_y1);
    cudaGetSymbolAddress((void**)&p_wq,  g_wq);
    cudaGetSymbolAddress((void**)&p_wk,  g_wk);
    cudaGetSymbolAddress((void**)&p_wv,  g_wv);
    cudaGetSymbolAddress((void**)&p_wp,  g_wp);
    cudaGetSymbolAddress((void**)&p_w1,  g_w1);
    cudaGetSymbolAddress((void**)&p_w2,  g_w2);

    // weight conversion fp32 -> bf16
    const int WSMALL = CDIM * CDIM / 4, WBIG = CDIM * FFNDIM / 4;
    f2bf_kernel<<<(WSMALL + 255) / 256, 256>>>(q_w,    p_wq, WSMALL);
    f2bf_kernel<<<(WSMALL + 255) / 256, 256>>>(k_w,    p_wk, WSMALL);
    f2bf_kernel<<<(WSMALL + 255) / 256, 256>>>(v_w,    p_wv, WSMALL);
    f2bf_kernel<<<(WSMALL + 255) / 256, 256>>>(proj_w, p_wp, WSMALL);
    f2bf_kernel<<<(WBIG   + 255) / 256, 256>>>(fc1_w,  p_w1, WBIG);
    f2bf_kernel<<<(WBIG   + 255) / 256, 256>>>(fc2_w,  p_w2, WBIG);

    // 1) LN1 + shift-roll + window partition (gather)
    ln_kernel<<<MTOK, 128>>>(hidden, ln1_g, ln1_b, p_xw, 1);

    // 2) QKV projections (bf16 HMMA)
    dim3 gq(CDIM / GBN, MTOK / GBM);
    mma_gemm<0, bf16><<<gq, 256>>>(p_xw, p_wq, q_b, nullptr, p_q, MTOK, CDIM, CDIM);
    mma_gemm<0, bf16><<<gq, 256>>>(p_xw, p_wk, k_b, nullptr, p_k, MTOK, CDIM, CDIM);
    mma_gemm<0, bf16><<<gq, 256>>>(p_xw, p_wv, v_b, nullptr, p_v, MTOK, CDIM, CDIM);

    // 3) windowed attention
    attn_kernel<<<dim3(TOTWIN, NHEADS), 256>>>(p_q, p_k, p_v, rpb, rpi, p_ctx);

    // 4) output projection + window-reverse + roll-back + residual (scatter)
    mma_gemm<2, float><<<gq, 256>>>(p_ctx, p_wp, proj_b, hidden, p_h, MTOK, CDIM, CDIM);

    // 5) LN2
    ln_kernel<<<MTOK, 128>>>(p_h, ln2_g, ln2_b, p_ln2, 0);

    // 6) fc1 + exact GELU
    mma_gemm<1, bf16><<<dim3(FFNDIM / GBN, MTOK / GBM), 256>>>(
        p_ln2, p_w1, fc1_b, nullptr, p_y1, MTOK, FFNDIM, CDIM);

    // 7) fc2 + residual -> final output
    mma_gemm<3, float><<<gq, 256>>>(p_y1, p_w2, fc2_b, p_h, out, MTOK, CDIM, FFNDIM);
}

// round 3
// speedup vs baseline: 3.2894x; 1.0417x over previous
#include <cuda_runtime.h>
#include <cuda_bf16.h>
#include <math.h>
#include <stdint.h>

// ---------------- problem constants ----------------
#define BATCH   8
#define HIMG    56
#define WIMG    56
#define CDIM    384
#define NHEADS  12
#define HDIM    32
#define WIN     7
#define NTOK    49
#define SHIFT_S 3
#define TOTWIN  512
#define MTOK    25088
#define FFNDIM  1536
#define QKVN    1152          // 3*CDIM

typedef __nv_bfloat16 bf16;

// ---------------- scratch (device globals; allocation-free) ----------------
__device__ bf16  g_xw  [MTOK * CDIM];
__device__ bf16  g_qkv [MTOK * QKVN];
__device__ bf16  g_ctx [MTOK * CDIM];
__device__ float g_h   [MTOK * CDIM];
__device__ bf16  g_ln2 [MTOK * CDIM];
__device__ bf16  g_y1  [MTOK * FFNDIM];
__device__ bf16  g_wqkv[CDIM * QKVN];
__device__ float g_bqkv[QKVN];
__device__ bf16  g_wp  [CDIM * CDIM];
__device__ bf16  g_w1  [CDIM * FFNDIM];
__device__ bf16  g_w2  [FFNDIM * CDIM];

// windowed row r <-> original token t (same map both directions)
__device__ __forceinline__ int win_row_to_token(int r) {
    int b    = r / (HIMG * WIMG);
    int rem  = r - b * (HIMG * WIMG);
    int widx = rem / NTOK;
    int tok  = rem - widx * NTOK;
    int wi = widx >> 3, wj = widx & 7;
    int i = tok / WIN, j = tok - i * WIN;
    int sh = wi * WIN + i + SHIFT_S; if (sh >= HIMG) sh -= HIMG;
    int sw = wj * WIN + j + SHIFT_S; if (sw >= WIMG) sw -= WIMG;
    return b * (HIMG * WIMG) + sh * WIMG + sw;
}

// ---------------- fp32 -> bf16 convert ----------------
__global__ void __launch_bounds__(256) f2bf_kernel(
    const float* __restrict__ src, bf16* __restrict__ dst, int n4)
{
    int i = blockIdx.x * blockDim.x + threadIdx.x;
    if (i < n4) {
        float4 v = ((const float4*)src)[i];
        bf16 o[4] = {__float2bfloat16(v.x), __float2bfloat16(v.y),
                     __float2bfloat16(v.z), __float2bfloat16(v.w)};
        *(uint64_t*)(dst + i * 4) = *(uint64_t*)o;
    }
}

// ---------------- pack q|k|v weights + biases ----------------
#define QKV_W4 (CDIM * QKVN / 4)   // 110592
__global__ void __launch_bounds__(256) pack_qkv_kernel(
    const float* __restrict__ qw, const float* __restrict__ kw,
    const float* __restrict__ vw, const float* __restrict__ qb,
    const float* __restrict__ kb, const float* __restrict__ vb,
    bf16* __restrict__ wout, float* __restrict__ bout)
{
    int i = blockIdx.x * blockDim.x + threadIdx.x;
    if (i < QKV_W4) {
        int row = i / (QKVN / 4);
        int col = (i % (QKVN / 4)) * 4;
        const float* src = (col < CDIM) ? qw : (col < 2 * CDIM ? kw : vw);
        int c = col - (col < CDIM ? 0 : (col < 2 * CDIM ? CDIM : 2 * CDIM));
        float4 v = *(const float4*)(src + (size_t)row * CDIM + c);
        bf16 o[4] = {__float2bfloat16(v.x), __float2bfloat16(v.y),
                     __float2bfloat16(v.z), __float2bfloat16(v.w)};
        *(uint64_t*)(wout + (size_t)i * 4) = *(uint64_t*)o;
    } else if (i < QKV_W4 + QKVN / 4) {
        int col = (i - QKV_W4) * 4;
        const float* src = (col < CDIM) ? qb : (col < 2 * CDIM ? kb : vb);
        int c = col - (col < CDIM ? 0 : (col < 2 * CDIM ? CDIM : 2 * CDIM));
        *(float4*)(bout + col) = *(const float4*)(src + c);
    }
}

// ---------------- LayerNorm (fp32 in, bf16 out) ----------------
__global__ void __launch_bounds__(128) ln_kernel(
    const float* __restrict__ x, const float* __restrict__ g,
    const float* __restrict__ b, bf16* __restrict__ out, int permute)
{
    int r = blockIdx.x;
    int t = permute ? win_row_to_token(r) : r;
    const float* xi = x + (size_t)t * CDIM;
    bf16*        yo = out + (size_t)r * CDIM;
    int tid = threadIdx.x;

    float v[3];
    float s = 0.f, ss = 0.f;
#pragma unroll
    for (int i = 0; i < 3; i++) {
        v[i] = xi[tid + i * 128];
        s += v[i]; ss += v[i] * v[i];
    }
#pragma unroll
    for (int o = 16; o; o >>= 1) {
        s  += __shfl_xor_sync(0xffffffffu, s,  o);
        ss += __shfl_xor_sync(0xffffffffu, ss, o);
    }
    __shared__ float red[8];
    __shared__ float stat[2];
    int wid = tid >> 5, lane = tid & 31;
    if (lane == 0) { red[wid] = s; red[4 + wid] = ss; }
    __syncthreads();
    if (tid == 0) {
        float S  = red[0] + red[1] + red[2] + red[3];
        float SS = red[4] + red[5] + red[6] + red[7];
        float mu = S * (1.0f / CDIM);
        float var = SS * (1.0f / CDIM) - mu * mu;
        stat[0] = mu;
        stat[1] = rsqrtf(var + 1e-5f);
    }
    __syncthreads();
    float mu = stat[0], rstd = stat[1];
#pragma unroll
    for (int i = 0; i < 3; i++) {
        int c = tid + i * 128;
        yo[c] = __float2bfloat16((v[i] - mu) * rstd * g[c] + b[c]);
    }
}

// ---------------- HMMA bf16 GEMM, 128x128x32 tile ----------------
// C = A[M,K] @ B[K,N] + bias, epilogues:
//  0: store   1: exact GELU   2: scatter+residual   3: residual
#define GBM 128
#define GBN 128
#define GBK 32
#define ASTR 40
#define BSTR 136

#define CP16(dst, src) \
    asm volatile("cp.async.ca.shared.global [%0], [%1], 16;\n" :: \
        "r"((uint32_t)__cvta_generic_to_shared(dst)), "l"(src))
#define CP_COMMIT()  asm volatile("cp.async.commit_group;\n" ::)
#define CP_WAIT(n)   asm volatile("cp.async.wait_group %0;\n" :: "n"(n))

__device__ __forceinline__ void ldm_x4(uint32_t* r, const void* p) {
    uint32_t a = (uint32_t)__cvta_generic_to_shared(p);
    asm volatile("ldmatrix.sync.aligned.m8n8.x4.shared.b16 {%0,%1,%2,%3},[%4];"
        : "=r"(r[0]), "=r"(r[1]), "=r"(r[2]), "=r"(r[3]) : "r"(a));
}
__device__ __forceinline__ void ldm_x4t(uint32_t* r, const void* p) {
    uint32_t a = (uint32_t)__cvta_generic_to_shared(p);
    asm volatile("ldmatrix.sync.aligned.m8n8.x4.trans.shared.b16 {%0,%1,%2,%3},[%4];"
        : "=r"(r[0]), "=r"(r[1]), "=r"(r[2]), "=r"(r[3]) : "r"(a));
}
#define MMA16816(d, a, b0, b1) \
    asm volatile("mma.sync.aligned.m16n8k16.row.col.f32.bf16.bf16.f32 " \
        "{%0,%1,%2,%3},{%4,%5,%6,%7},{%8,%9},{%0,%1,%2,%3};" \
        : "+f"(d[0]), "+f"(d[1]), "+f"(d[2]), "+f"(d[3]) \
        : "r"(a[0]), "r"(a[1]), "r"(a[2]), "r"(a[3]), "r"(b0), "r"(b1))

template <int EPI, typename OutT>
__global__ void __launch_bounds__(256) mma_gemm(
    const bf16* __restrict__ A, const bf16* __restrict__ B,
    const float* __restrict__ bias, const float* __restrict__ add,
    OutT* __restrict__ C, int M, int N, int K)
{
    __shared__ __align__(16) bf16 As[2][GBM][ASTR];
    __shared__ __align__(16) bf16 Bs[2][GBK][BSTR];

    int t = threadIdx.x;
    int m0 = blockIdx.y * GBM, n0 = blockIdx.x * GBN;

    int ar = t >> 2, aseg = (t & 3) * 8;         // A: 64 rows x 32 cols per cp pass
    int br = t >> 3, bseg = (t & 7) * 16;        // B: 32 rows x 128 cols, 2 cp per thread
    const bf16* Ag = A + (size_t)(m0 + ar) * K + aseg;
    const bf16* Bg = B + (size_t)br * N + n0 + bseg;

    int lane = t & 31, w = t >> 5;
    int m0w = (w >> 1) * 32, nw = (w & 1) * 64;  // warp tile 32x64
    int lrow = (lane & 7) + (lane & 8);
    int lcol = (lane & 16) >> 1;

    float acc[2][8][4] = {};

    int nk = K / GBK;
    {
        CP16(&As[0][ar][aseg], Ag);
        CP16(&As[0][ar + 64][aseg], Ag + (size_t)64 * K);
        CP16(&Bs[0][br][bseg], Bg);
        CP16(&Bs[0][br][bseg + 8], Bg + 8);
        CP_COMMIT();
    }

    int buf = 0;
    for (int i = 0; i < nk; i++) {
        if (i + 1 < nk) {
            int k0 = (i + 1) * GBK;
            CP16(&As[buf ^ 1][ar][aseg], Ag + k0);
            CP16(&As[buf ^ 1][ar + 64][aseg], Ag + (size_t)64 * K + k0);
            CP16(&Bs[buf ^ 1][br][bseg], Bg + (size_t)k0 * N);
            CP16(&Bs[buf ^ 1][br][bseg + 8], Bg + (size_t)k0 * N + 8);
            CP_COMMIT();
            CP_WAIT(1);
        } else {
            CP_WAIT(0);
        }
        __syncthreads();

#pragma unroll
        for (int kk = 0; kk < GBK; kk += 16) {
            uint32_t a[2][4], b[4][4];
#pragma unroll
            for (int mi = 0; mi < 2; mi++)
                ldm_x4(a[mi], &As[buf][m0w + mi * 16 + lrow][kk + lcol]);
#pragma unroll
            for (int nj = 0; nj < 4; nj++)
                ldm_x4t(b[nj], &Bs[buf][kk + lrow][nw + nj * 16 + lcol]);
#pragma unroll
            for (int mi = 0; mi < 2; mi++) {
#pragma unroll
                for (int nt = 0; nt < 8; nt++)
                    MMA16816(acc[mi][nt], a[mi],
                             b[nt >> 1][(nt & 1) * 2], b[nt >> 1][(nt & 1) * 2 + 1]);
            }
        }
        __syncthreads();
        buf ^= 1;
    }

    // epilogue
#pragma unroll
    for (int mi = 0; mi < 2; mi++) {
        int rbase = m0 + m0w + mi * 16 + (lane >> 2);
#pragma unroll
        for (int h2 = 0; h2 < 2; h2++) {
            int row = rbase + 8 * h2;
            int orow = (EPI == 2) ? win_row_to_token(row) : row;
#pragma unroll
            for (int nt = 0; nt < 8; nt++) {
                int col = n0 + nw + nt * 8 + (lane & 3) * 2;
                float v0 = acc[mi][nt][2 * h2 + 0] + bias[col];
                float v1 = acc[mi][nt][2 * h2 + 1] + bias[col + 1];
                if (EPI == 1) {
                    v0 = 0.5f * v0 * (1.0f + erff(v0 * 0.7071067811865475f));
                    v1 = 0.5f * v1 * (1.0f + erff(v1 * 0.7071067811865475f));
                } else if (EPI == 2 || EPI == 3) {
                    const float* ap = add + (size_t)orow * N + col;
                    v0 += ap[0];
                    v1 += ap[1];
                }
                OutT* cp = C + (size_t)orow * N + col;
                if (sizeof(OutT) == 2) {
                    __nv_bfloat162 pk;
                    pk.x = __float2bfloat16(v0);
                    pk.y = __float2bfloat16(v1);
                    *(__nv_bfloat162*)cp = pk;
                } else {
                    float2 pk = make_float2(v0, v1);
                    *(float2*)cp = pk;
                }
            }
        }
    }
}

// ---------------- fused window attention (reads packed QKV) ----------------
__global__ void __launch_bounds__(256) attn_kernel(
    const bf16* __restrict__ QKV, const float* __restrict__ rpb,
    const int* __restrict__ rpi, bf16* __restrict__ O)
{
    int win = blockIdx.x;
    int h   = blockIdx.y;
    int tid = threadIdx.x;

    __shared__ float qs[NTOK][HDIM];
    __shared__ float ks[NTOK][HDIM];
    __shared__ float vs[NTOK][HDIM];
    __shared__ float sc[NTOK][NTOK + 1];
    __shared__ int   codes[NTOK];

    int widx = win & 63;
    int wi = widx >> 3, wj = widx & 7;
    if (tid < NTOK) {
        int i = tid / WIN, j = tid - i * WIN;
        int r = wi * WIN + i, c = wj * WIN + j;
        int rc = (r < HIMG - WIN) ? 0 : (r < HIMG - SHIFT_S ? 1 : 2);
        int cc = (c < WIMG - WIN) ? 0 : (c < WIMG - SHIFT_S ? 1 : 2);
        codes[tid] = rc * 3 + cc;
    }

    const size_t qbase = (size_t)win * NTOK * QKVN + h * HDIM;
    for (int idx = tid; idx < NTOK * HDIM; idx += 256) {
        int n = idx >> 5, d = idx & 31;
        size_t gi = qbase + (size_t)n * QKVN + d;
        qs[n][d] = __bfloat162float(QKV[gi]);
        ks[n][d] = __bfloat162float(QKV[gi + CDIM]);
        vs[n][d] = __bfloat162float(QKV[gi + 2 * CDIM]);
    }
    __syncthreads();

    const float scale = 0.17677669529663687f;  // 1/sqrt(32)
    for (int idx = tid; idx < NTOK * NTOK; idx += 256) {
        int n = idx / NTOK, m = idx - n * NTOK;
        float s = 0.f;
#pragma unroll
        for (int d = 0; d < HDIM; d++) s += qs[n][d] * ks[m][d];
        s = s * scale + rpb[rpi[idx] * NHEADS + h];
        if (codes[n] != codes[m]) s -= 100.0f;
        sc[n][m] = s;
    }
    __syncthreads();

    int wid = tid >> 5, lane = tid & 31;
    for (int n = wid; n < NTOK; n += 8) {
        float v0 = sc[n][lane];
        float v1 = (lane + 32 < NTOK) ? sc[n][lane + 32] : -1e30f;
        float mx = fmaxf(v0, v1);
#pragma unroll
        for (int o = 16; o; o >>= 1) mx = fmaxf(mx, __shfl_xor_sync(0xffffffffu, mx, o));
        float e0 = expf(v0 - mx);
        float e1 = (lane + 32 < NTOK) ? expf(v1 - mx) : 0.f;
        float sum = e0 + e1;
#pragma unroll
        for (int o = 16; o; o >>= 1) sum += __shfl_xor_sync(0xffffffffu, sum, o);
        float inv = 1.0f / sum;
        sc[n][lane] = e0 * inv;
        if (lane + 32 < NTOK) sc[n][lane + 32] = e1 * inv;
    }
    __syncthreads();

    const size_t obase = (size_t)win * NTOK * CDIM + h * HDIM;
    for (int idx = tid; idx < NTOK * HDIM; idx += 256) {
        int n = idx >> 5, d = idx & 31;
        float s = 0.f;
#pragma unroll
        for (int m = 0; m < NTOK; m++) s += sc[n][m] * vs[m][d];
        O[obase + (size_t)n * CDIM + d] = __float2bfloat16(s);
    }
}

// ---------------- launch ----------------
extern "C" void kernel_launch(void* const* d_in, const int* in_sizes, int n_in,
                              void* d_out, int out_size)
{
    const float* hidden  = (const float*)d_in[0];
    const float* ln1_g   = (const float*)d_in[1];
    const float* ln1_b   = (const float*)d_in[2];
    const float* q_w     = (const float*)d_in[3];
    const float* q_b     = (const float*)d_in[4];
    const float* k_w     = (const float*)d_in[5];
    const float* k_b     = (const float*)d_in[6];
    const float* v_w     = (const float*)d_in[7];
    const float* v_b     = (const float*)d_in[8];
    const float* rpb     = (const float*)d_in[9];
    const int*   rpi     = (const int*)  d_in[10];
    const float* proj_w  = (const float*)d_in[11];
    const float* proj_b  = (const float*)d_in[12];
    const float* ln2_g   = (const float*)d_in[13];
    const float* ln2_b   = (const float*)d_in[14];
    const float* fc1_w   = (const float*)d_in[15];
    const float* fc1_b   = (const float*)d_in[16];
    const float* fc2_w   = (const float*)d_in[17];
    const float* fc2_b   = (const float*)d_in[18];
    float* out = (float*)d_out;

    bf16 *p_xw, *p_qkv, *p_ctx, *p_ln2, *p_y1;
    bf16 *p_wqkv, *p_wp, *p_w1, *p_w2;
    float *p_h, *p_bqkv;
    cudaGetSymbolAddress((void**)&p_xw,   g_xw);
    cudaGetSymbolAddress((void**)&p_qkv,  g_qkv);
    cudaGetSymbolAddress((void**)&p_ctx,  g_ctx);
    cudaGetSymbolAddress((void**)&p_h,    g_h);
    cudaGetSymbolAddress((void**)&p_ln2,  g_ln2);
    cudaGetSymbolAddress((void**)&p_y1,   g_y1);
    cudaGetSymbolAddress((void**)&p_wqkv, g_wqkv);
    cudaGetSymbolAddress((void**)&p_bqkv, g_bqkv);
    cudaGetSymbolAddress((void**)&p_wp,   g_wp);
    cudaGetSymbolAddress((void**)&p_w1,   g_w1);
    cudaGetSymbolAddress((void**)&p_w2,   g_w2);

    // weight packing / conversion
    const int WSMALL = CDIM * CDIM / 4, WBIG = CDIM * FFNDIM / 4;
    pack_qkv_kernel<<<(QKV_W4 + QKVN / 4 + 255) / 256, 256>>>(
        q_w, k_w, v_w, q_b, k_b, v_b, p_wqkv, p_bqkv);
    f2bf_kernel<<<(WSMALL + 255) / 256, 256>>>(proj_w, p_wp, WSMALL);
    f2bf_kernel<<<(WBIG   + 255) / 256, 256>>>(fc1_w,  p_w1, WBIG);
    f2bf_kernel<<<(WBIG   + 255) / 256, 256>>>(fc2_w,  p_w2, WBIG);

    // 1) LN1 + shift-roll + window partition (gather)
    ln_kernel<<<MTOK, 128>>>(hidden, ln1_g, ln1_b, p_xw, 1);

    // 2) fused QKV projection
    mma_gemm<0, bf16><<<dim3(QKVN / GBN, MTOK / GBM), 256>>>(
        p_xw, p_wqkv, p_bqkv, nullptr, p_qkv, MTOK, QKVN, CDIM);

    // 3) windowed attention
    attn_kernel<<<dim3(TOTWIN, NHEADS), 256>>>(p_qkv, rpb, rpi, p_ctx);

    // 4) output projection + window-reverse + roll-back + residual (scatter)
    mma_gemm<2, float><<<dim3(CDIM / GBN, MTOK / GBM), 256>>>(
        p_ctx, p_wp, proj_b, hidden, p_h, MTOK, CDIM, CDIM);

    // 5) LN2
    ln_kernel<<<MTOK, 128>>>(p_h, ln2_g, ln2_b, p_ln2, 0);

    // 6) fc1 + exact GELU
    mma_gemm<1, bf16><<<dim3(FFNDIM / GBN, MTOK / GBM), 256>>>(
        p_ln2, p_w1, fc1_b, nullptr, p_y1, MTOK, FFNDIM, CDIM);

    // 7) fc2 + residual -> final output
    mma_gemm<3, float><<<dim3(CDIM / GBN, MTOK / GBM), 256>>>(
        p_y1, p_w2, fc2_b, p_h, out, MTOK, CDIM, FFNDIM);
}

// round 4
// speedup vs baseline: 6.8126x; 2.0711x over previous
#include <cuda_runtime.h>
#include <cuda_bf16.h>
#include <math.h>
#include <stdint.h>

// ---------------- problem constants ----------------
#define BATCH   8
#define HIMG    56
#define WIMG    56
#define CDIM    384
#define NHEADS  12
#define HDIM    32
#define WIN     7
#define NTOK    49
#define SHIFT_S 3
#define TOTWIN  512
#define MTOK    25088
#define FFNDIM  1536
#define QKVN    1152          // 3*CDIM

typedef __nv_bfloat16 bf16;

// ---------------- scratch (device globals; allocation-free) ----------------
__device__ bf16  g_xw  [MTOK * CDIM];
__device__ bf16  g_qkv [MTOK * QKVN];
__device__ bf16  g_ctx [MTOK * CDIM];
__device__ float g_h   [MTOK * CDIM];
__device__ bf16  g_ln2 [MTOK * CDIM];
__device__ bf16  g_y1  [MTOK * FFNDIM];
__device__ bf16  g_wqkv[CDIM * QKVN];
__device__ float g_bqkv[QKVN];
__device__ bf16  g_wp  [CDIM * CDIM];
__device__ bf16  g_w1  [CDIM * FFNDIM];
__device__ bf16  g_w2  [FFNDIM * CDIM];
__device__ bf16  g_bias[4 * NHEADS * 64 * 64];   // [type][head][n(64)][m(64)]

// windowed row r <-> original token t (same map both directions)
__device__ __forceinline__ int win_row_to_token(int r) {
    int b    = r / (HIMG * WIMG);
    int rem  = r - b * (HIMG * WIMG);
    int widx = rem / NTOK;
    int tok  = rem - widx * NTOK;
    int wi = widx >> 3, wj = widx & 7;
    int i = tok / WIN, j = tok - i * WIN;
    int sh = wi * WIN + i + SHIFT_S; if (sh >= HIMG) sh -= HIMG;
    int sw = wj * WIN + j + SHIFT_S; if (sw >= WIMG) sw -= WIMG;
    return b * (HIMG * WIMG) + sh * WIMG + sw;
}

// ---------------- fp32 -> bf16 convert ----------------
__global__ void __launch_bounds__(256) f2bf_kernel(
    const float* __restrict__ src, bf16* __restrict__ dst, int n4)
{
    int i = blockIdx.x * blockDim.x + threadIdx.x;
    if (i < n4) {
        float4 v = ((const float4*)src)[i];
        bf16 o[4] = {__float2bfloat16(v.x), __float2bfloat16(v.y),
                     __float2bfloat16(v.z), __float2bfloat16(v.w)};
        *(uint64_t*)(dst + i * 4) = *(uint64_t*)o;
    }
}

// ---------------- pack q|k|v weights + biases ----------------
#define QKV_W4 (CDIM * QKVN / 4)
__global__ void __launch_bounds__(256) pack_qkv_kernel(
    const float* __restrict__ qw, const float* __restrict__ kw,
    const float* __restrict__ vw, const float* __restrict__ qb,
    const float* __restrict__ kb, const float* __restrict__ vb,
    bf16* __restrict__ wout, float* __restrict__ bout)
{
    int i = blockIdx.x * blockDim.x + threadIdx.x;
    if (i < QKV_W4) {
        int row = i / (QKVN / 4);
        int col = (i % (QKVN / 4)) * 4;
        const float* src = (col < CDIM) ? qw : (col < 2 * CDIM ? kw : vw);
        int c = col - (col < CDIM ? 0 : (col < 2 * CDIM ? CDIM : 2 * CDIM));
        float4 v = *(const float4*)(src + (size_t)row * CDIM + c);
        bf16 o[4] = {__float2bfloat16(v.x), __float2bfloat16(v.y),
                     __float2bfloat16(v.z), __float2bfloat16(v.w)};
        *(uint64_t*)(wout + (size_t)i * 4) = *(uint64_t*)o;
    } else if (i < QKV_W4 + QKVN / 4) {
        int col = (i - QKV_W4) * 4;
        const float* src = (col < CDIM) ? qb : (col < 2 * CDIM ? kb : vb);
        int c = col - (col < CDIM ? 0 : (col < 2 * CDIM ? CDIM : 2 * CDIM));
        *(float4*)(bout + col) = *(const float4*)(src + c);
    }
}

// ---------------- precompute attention bias+mask tiles ----------------
// g_bias[type][h][n 64][m 64]: rpb gather + shift mask; m>=49 -> -1e30
__global__ void __launch_bounds__(256) bias_kernel(
    const float* __restrict__ rpb, const int* __restrict__ rpi,
    bf16* __restrict__ out)
{
    int type = blockIdx.x, h = blockIdx.y;
    for (int idx = threadIdx.x; idx < 64 * 64; idx += 256) {
        int n = idx >> 6, m = idx & 63;
        float v;
        if (m >= 49)      v = -1e30f;
        else if (n >= 49) v = 0.f;
        else {
            v = rpb[rpi[n * 49 + m] * NHEADS + h];
            int ni = n / 7, nj = n % 7, mi = m / 7, mj = m % 7;
            int cn = ((type & 2) ? (ni < 4 ? 1 : 2) : 0) * 3 + ((type & 1) ? (nj < 4 ? 1 : 2) : 0);
            int cm = ((type & 2) ? (mi < 4 ? 1 : 2) : 0) * 3 + ((type & 1) ? (mj < 4 ? 1 : 2) : 0);
            if (cn != cm) v -= 100.0f;
        }
        out[(((size_t)type * NHEADS + h) * 64 + n) * 64 + m] = __float2bfloat16(v);
    }
}

// ---------------- LayerNorm (fp32 in, bf16 out) ----------------
__global__ void __launch_bounds__(128) ln_kernel(
    const float* __restrict__ x, const float* __restrict__ g,
    const float* __restrict__ b, bf16* __restrict__ out, int permute)
{
    int r = blockIdx.x;
    int t = permute ? win_row_to_token(r) : r;
    const float* xi = x + (size_t)t * CDIM;
    bf16*        yo = out + (size_t)r * CDIM;
    int tid = threadIdx.x;

    float v[3];
    float s = 0.f, ss = 0.f;
#pragma unroll
    for (int i = 0; i < 3; i++) {
        v[i] = xi[tid + i * 128];
        s += v[i]; ss += v[i] * v[i];
    }
#pragma unroll
    for (int o = 16; o; o >>= 1) {
        s  += __shfl_xor_sync(0xffffffffu, s,  o);
        ss += __shfl_xor_sync(0xffffffffu, ss, o);
    }
    __shared__ float red[8];
    __shared__ float stat[2];
    int wid = tid >> 5, lane = tid & 31;
    if (lane == 0) { red[wid] = s; red[4 + wid] = ss; }
    __syncthreads();
    if (tid == 0) {
        float S  = red[0] + red[1] + red[2] + red[3];
        float SS = red[4] + red[5] + red[6] + red[7];
        float mu = S * (1.0f / CDIM);
        float var = SS * (1.0f / CDIM) - mu * mu;
        stat[0] = mu;
        stat[1] = rsqrtf(var + 1e-5f);
    }
    __syncthreads();
    float mu = stat[0], rstd = stat[1];
#pragma unroll
    for (int i = 0; i < 3; i++) {
        int c = tid + i * 128;
        yo[c] = __float2bfloat16((v[i] - mu) * rstd * g[c] + b[c]);
    }
}

// ---------------- mma helpers ----------------
#define CP16(dst, src) \
    asm volatile("cp.async.ca.shared.global [%0], [%1], 16;\n" :: \
        "r"((uint32_t)__cvta_generic_to_shared(dst)), "l"(src))
#define CP_COMMIT()  asm volatile("cp.async.commit_group;\n" ::)
#define CP_WAIT(n)   asm volatile("cp.async.wait_group %0;\n" :: "n"(n))

__device__ __forceinline__ void ldm_x4(uint32_t* r, const void* p) {
    uint32_t a = (uint32_t)__cvta_generic_to_shared(p);
    asm volatile("ldmatrix.sync.aligned.m8n8.x4.shared.b16 {%0,%1,%2,%3},[%4];"
        : "=r"(r[0]), "=r"(r[1]), "=r"(r[2]), "=r"(r[3]) : "r"(a));
}
__device__ __forceinline__ void ldm_x4t(uint32_t* r, const void* p) {
    uint32_t a = (uint32_t)__cvta_generic_to_shared(p);
    asm volatile("ldmatrix.sync.aligned.m8n8.x4.trans.shared.b16 {%0,%1,%2,%3},[%4];"
        : "=r"(r[0]), "=r"(r[1]), "=r"(r[2]), "=r"(r[3]) : "r"(a));
}
#define MMA16816(d, a, b0, b1) \
    asm volatile("mma.sync.aligned.m16n8k16.row.col.f32.bf16.bf16.f32 " \
        "{%0,%1,%2,%3},{%4,%5,%6,%7},{%8,%9},{%0,%1,%2,%3};" \
        : "+f"(d[0]), "+f"(d[1]), "+f"(d[2]), "+f"(d[3]) \
        : "r"(a[0]), "r"(a[1]), "r"(a[2]), "r"(a[3]), "r"(b0), "r"(b1))

__device__ __forceinline__ uint32_t packbf(float lo, float hi) {
    __nv_bfloat162 h = __floats2bfloat162_rn(lo, hi);
    return *(uint32_t*)&h;
}

// ---------------- HMMA bf16 GEMM, 128x128x32, 3-stage, XOR-swizzled --------
#define GBM 128
#define GBN 128
#define GBK 32

template <int EPI, typename OutT>
__global__ void __launch_bounds__(256) mma_gemm(
    const bf16* __restrict__ A, const bf16* __restrict__ B,
    const float* __restrict__ bias, const float* __restrict__ add,
    OutT* __restrict__ C, int M, int N, int K)
{
    __shared__ __align__(16) bf16 As[3][GBM * GBK];   // swizzled [row][32]
    __shared__ __align__(16) bf16 Bs[3][GBK * GBN];   // swizzled [k][128]

    int t = threadIdx.x;
    int m0 = blockIdx.y * GBM, n0 = blockIdx.x * GBN;

    int ar = t >> 2, acw = t & 3;                 // A: row, 16B chunk
    int br = t >> 3, bcw = (t & 7) * 2;           // B: k-row, chunk pair
    const bf16* Ag = A + (size_t)(m0 + ar) * K + acw * 8;
    const bf16* Bg = B + (size_t)br * N + n0 + bcw * 8;

    int aswz = (ar >> 1) & 3;                     // same for row ar and ar+64
    int a_off0 = ar * 32 + ((acw ^ aswz) << 3);
    int a_off1 = (ar + 64) * 32 + ((acw ^ aswz) << 3);
    int b_off0 = br * 128 + (((bcw)     ^ (br & 7)) << 3);
    int b_off1 = br * 128 + (((bcw + 1) ^ (br & 7)) << 3);

    int lane = t & 31, w = t >> 5;
    int m0w = (w >> 1) * 32, nw = (w & 1) * 64;
    int lrow = (lane & 7) + (lane & 8);
    int lcol = (lane & 16) >> 1;

    float acc[2][8][4] = {};

    int nk = K / GBK;
    // prologue: stages 0,1
#pragma unroll
    for (int s = 0; s < 2; s++) {
        int k0 = s * GBK;
        CP16(&As[s][a_off0], Ag + k0);
        CP16(&As[s][a_off1], Ag + (size_t)64 * K + k0);
        CP16(&Bs[s][b_off0], Bg + (size_t)k0 * N);
        CP16(&Bs[s][b_off1], Bg + (size_t)k0 * N + 8);
        CP_COMMIT();
    }

    for (int i = 0; i < nk; i++) {
        if (i + 1 < nk) { CP_WAIT(1); } else { CP_WAIT(0); }
        __syncthreads();
        if (i + 2 < nk) {
            int st = (i + 2) % 3;
            int k0 = (i + 2) * GBK;
            CP16(&As[st][a_off0], Ag + k0);
            CP16(&As[st][a_off1], Ag + (size_t)64 * K + k0);
            CP16(&Bs[st][b_off0], Bg + (size_t)k0 * N);
            CP16(&Bs[st][b_off1], Bg + (size_t)k0 * N + 8);
            CP_COMMIT();
        }
        int cs = i % 3;
#pragma unroll
        for (int kk = 0; kk < GBK; kk += 16) {
            uint32_t a[2][4], b[4][4];
#pragma unroll
            for (int mi = 0; mi < 2; mi++) {
                int R = m0w + mi * 16 + lrow;
                int cr = (kk + lcol) >> 3;
                ldm_x4(a[mi], &As[cs][R * 32 + ((cr ^ ((R >> 1) & 3)) << 3)]);
            }
#pragma unroll
            for (int nj = 0; nj < 4; nj++) {
                int Kr = kk + lrow;
                int cn = (nw + nj * 16 + lcol) >> 3;
                ldm_x4t(b[nj], &Bs[cs][Kr * 128 + ((cn ^ (Kr & 7)) << 3)]);
            }
#pragma unroll
            for (int mi = 0; mi < 2; mi++) {
#pragma unroll
                for (int nt = 0; nt < 8; nt++)
                    MMA16816(acc[mi][nt], a[mi],
                             b[nt >> 1][(nt & 1) * 2], b[nt >> 1][(nt & 1) * 2 + 1]);
            }
        }
    }

    // epilogue
#pragma unroll
    for (int mi = 0; mi < 2; mi++) {
        int rbase = m0 + m0w + mi * 16 + (lane >> 2);
#pragma unroll
        for (int h2 = 0; h2 < 2; h2++) {
            int row = rbase + 8 * h2;
            int orow = (EPI == 2) ? win_row_to_token(row) : row;
#pragma unroll
            for (int nt = 0; nt < 8; nt++) {
                int col = n0 + nw + nt * 8 + (lane & 3) * 2;
                float v0 = acc[mi][nt][2 * h2 + 0] + bias[col];
                float v1 = acc[mi][nt][2 * h2 + 1] + bias[col + 1];
                if (EPI == 1) {
                    v0 = 0.5f * v0 * (1.0f + erff(v0 * 0.7071067811865475f));
                    v1 = 0.5f * v1 * (1.0f + erff(v1 * 0.7071067811865475f));
                } else if (EPI == 2 || EPI == 3) {
                    const float* ap = add + (size_t)orow * N + col;
                    v0 += ap[0];
                    v1 += ap[1];
                }
                OutT* cp = C + (size_t)orow * N + col;
                if (sizeof(OutT) == 2) {
                    __nv_bfloat162 pk;
                    pk.x = __float2bfloat16(v0);
                    pk.y = __float2bfloat16(v1);
                    *(__nv_bfloat162*)cp = pk;
                } else {
                    float2 pk = make_float2(v0, v1);
                    *(float2*)cp = pk;
                }
            }
        }
    }
}

// ---------------- tensor-core window attention ----------------
// 1 block / window, 8 warps: 2 heads per pass (4 warps each), 6 passes.
__global__ void __launch_bounds__(256) attn_mma_kernel(
    const bf16* __restrict__ QKV, const bf16* __restrict__ bias_all,
    bf16* __restrict__ O)
{
    __shared__ __align__(16) bf16 sQ[2][64][40];
    __shared__ __align__(16) bf16 sK[2][64][40];
    __shared__ __align__(16) bf16 sV[2][64][40];
    __shared__ __align__(16) bf16 sB[2][64][72];

    int win = blockIdx.x, t = threadIdx.x;
    int widx = win & 63;
    int type = (((widx >> 3) == 7) ? 2 : 0) + (((widx & 7) == 7) ? 1 : 0);

    // zero K,V pad rows (49..63) once
    for (int i = t; i < 2 * 15 * 40; i += 256) {
        int hs = i / 600, rem = i % 600;
        int row = 49 + rem / 40, col = rem % 40;
        sK[hs][row][col] = __float2bfloat16(0.f);
        sV[hs][row][col] = __float2bfloat16(0.f);
    }

    int lane = t & 31, w = t >> 5;
    int hs = w >> 2, ww = w & 3;
    int r0 = ww * 16;
    int lrow = (lane & 7) + (lane & 8);
    int lcol = (lane & 16) >> 1;
    int qr = lane >> 2, qc = lane & 3;
    const float scale = 0.17677669529663687f;  // 1/sqrt(32)

    int lr = t >> 2, lc = t & 3;   // load mapping

    for (int p = 0; p < 6; p++) {
        __syncthreads();           // prior pass done reading smem
        // --- load 2 heads of Q,K,V + bias tiles ---
        if (lr < 49) {
            const bf16* src = QKV + (size_t)(win * NTOK + lr) * QKVN + lc * 8;
#pragma unroll
            for (int hh = 0; hh < 2; hh++) {
                int h = p * 2 + hh;
                CP16(&sQ[hh][lr][lc * 8], src + h * HDIM);
                CP16(&sK[hh][lr][lc * 8], src + h * HDIM + CDIM);
                CP16(&sV[hh][lr][lc * 8], src + h * HDIM + 2 * CDIM);
            }
        }
#pragma unroll
        for (int hh = 0; hh < 2; hh++) {
            int h = p * 2 + hh;
            const bf16* bsrc = bias_all + (((size_t)type * NHEADS + h) * 64 + lr) * 64;
            CP16(&sB[hh][lr][lc * 8], bsrc + lc * 8);
            CP16(&sB[hh][lr][(lc + 4) * 8], bsrc + (lc + 4) * 8);
        }
        CP_COMMIT(); CP_WAIT(0);
        __syncthreads();

        // --- S = Q K^T (16 rows per warp, 64 cols) ---
        float acc[8][4] = {};
#pragma unroll
        for (int kc = 0; kc < 32; kc += 16) {
            uint32_t a[4];
            ldm_x4(a, &sQ[hs][r0 + lrow][kc + lcol]);
            uint32_t bb[4][4];
#pragma unroll
            for (int nj = 0; nj < 4; nj++)
                ldm_x4(bb[nj], &sK[hs][nj * 16 + lrow][kc + lcol]);
#pragma unroll
            for (int nj = 0; nj < 4; nj++) {
                MMA16816(acc[nj * 2 + 0], a, bb[nj][0], bb[nj][2]);
                MMA16816(acc[nj * 2 + 1], a, bb[nj][1], bb[nj][3]);
            }
        }
        // --- scale + bias ---
#pragma unroll
        for (int cj = 0; cj < 4; cj++) {
            uint32_t bf[4];
            ldm_x4(bf, &sB[hs][r0 + lrow][cj * 16 + lcol]);
            float2 f0 = __bfloat1622float2(*(__nv_bfloat162*)&bf[0]);
            float2 f1 = __bfloat1622float2(*(__nv_bfloat162*)&bf[1]);
            float2 f2 = __bfloat1622float2(*(__nv_bfloat162*)&bf[2]);
            float2 f3 = __bfloat1622float2(*(__nv_bfloat162*)&bf[3]);
            acc[2 * cj][0] = acc[2 * cj][0] * scale + f0.x;
            acc[2 * cj][1] = acc[2 * cj][1] * scale + f0.y;
            acc[2 * cj][2] = acc[2 * cj][2] * scale + f1.x;
            acc[2 * cj][3] = acc[2 * cj][3] * scale + f1.y;
            acc[2 * cj + 1][0] = acc[2 * cj + 1][0] * scale + f2.x;
            acc[2 * cj + 1][1] = acc[2 * cj + 1][1] * scale + f2.y;
            acc[2 * cj + 1][2] = acc[2 * cj + 1][2] * scale + f3.x;
            acc[2 * cj + 1][3] = acc[2 * cj + 1][3] * scale + f3.y;
        }
        // --- softmax (rows qr and qr+8 of this warp tile) ---
        float mx1 = -1e30f, mx2 = -1e30f;
#pragma unroll
        for (int nt = 0; nt < 8; nt++) {
            mx1 = fmaxf(mx1, fmaxf(acc[nt][0], acc[nt][1]));
            mx2 = fmaxf(mx2, fmaxf(acc[nt][2], acc[nt][3]));
        }
        mx1 = fmaxf(mx1, __shfl_xor_sync(0xffffffffu, mx1, 1));
        mx1 = fmaxf(mx1, __shfl_xor_sync(0xffffffffu, mx1, 2));
        mx2 = fmaxf(mx2, __shfl_xor_sync(0xffffffffu, mx2, 1));
        mx2 = fmaxf(mx2, __shfl_xor_sync(0xffffffffu, mx2, 2));
        float sum1 = 0.f, sum2 = 0.f;
#pragma unroll
        for (int nt = 0; nt < 8; nt++) {
            acc[nt][0] = __expf(acc[nt][0] - mx1);
            acc[nt][1] = __expf(acc[nt][1] - mx1);
            acc[nt][2] = __expf(acc[nt][2] - mx2);
            acc[nt][3] = __expf(acc[nt][3] - mx2);
            sum1 += acc[nt][0] + acc[nt][1];
            sum2 += acc[nt][2] + acc[nt][3];
        }
        sum1 += __shfl_xor_sync(0xffffffffu, sum1, 1);
        sum1 += __shfl_xor_sync(0xffffffffu, sum1, 2);
        sum2 += __shfl_xor_sync(0xffffffffu, sum2, 1);
        sum2 += __shfl_xor_sync(0xffffffffu, sum2, 2);
        float inv1 = 1.0f / sum1, inv2 = 1.0f / sum2;

        // --- ctx = P V  (P from registers as A-fragments) ---
        float o[4][4] = {};
#pragma unroll
        for (int kc2 = 0; kc2 < 4; kc2++) {
            uint32_t pa[4];
            pa[0] = packbf(acc[2 * kc2][0],     acc[2 * kc2][1]);
            pa[1] = packbf(acc[2 * kc2][2],     acc[2 * kc2][3]);
            pa[2] = packbf(acc[2 * kc2 + 1][0], acc[2 * kc2 + 1][1]);
            pa[3] = packbf(acc[2 * kc2 + 1][2], acc[2 * kc2 + 1][3]);
#pragma unroll
            for (int nj = 0; nj < 2; nj++) {
                uint32_t vb[4];
                ldm_x4t(vb, &sV[hs][kc2 * 16 + lrow][nj * 16 + lcol]);
                MMA16816(o[nj * 2 + 0], pa, vb[0], vb[1]);
                MMA16816(o[nj * 2 + 1], pa, vb[2], vb[3]);
            }
        }
        // --- store ctx rows (<49) ---
        int H = p * 2 + hs;
        int row1 = r0 + qr, row2 = r0 + qr + 8;
        if (row1 < NTOK) {
            bf16* dst = O + (size_t)(win * NTOK + row1) * CDIM + H * HDIM + qc * 2;
#pragma unroll
            for (int nt = 0; nt < 4; nt++) {
                __nv_bfloat162 pk;
                pk.x = __float2bfloat16(o[nt][0] * inv1);
                pk.y = __float2bfloat16(o[nt][1] * inv1);
                *(__nv_bfloat162*)(dst + nt * 8) = pk;
            }
        }
        if (row2 < NTOK) {
            bf16* dst = O + (size_t)(win * NTOK + row2) * CDIM + H * HDIM + qc * 2;
#pragma unroll
            for (int nt = 0; nt < 4; nt++) {
                __nv_bfloat162 pk;
                pk.x = __float2bfloat16(o[nt][2] * inv2);
                pk.y = __float2bfloat16(o[nt][3] * inv2);
                *(__nv_bfloat162*)(dst + nt * 8) = pk;
            }
        }
    }
}

// ---------------- launch ----------------
extern "C" void kernel_launch(void* const* d_in, const int* in_sizes, int n_in,
                              void* d_out, int out_size)
{
    const float* hidden  = (const float*)d_in[0];
    const float* ln1_g   = (const float*)d_in[1];
    const float* ln1_b   = (const float*)d_in[2];
    const float* q_w     = (const float*)d_in[3];
    const float* q_b     = (const float*)d_in[4];
    const float* k_w     = (const float*)d_in[5];
    const float* k_b     = (const float*)d_in[6];
    const float* v_w     = (const float*)d_in[7];
    const float* v_b     = (const float*)d_in[8];
    const float* rpb     = (const float*)d_in[9];
    const int*   rpi     = (const int*)  d_in[10];
    const float* proj_w  = (const float*)d_in[11];
    const float* proj_b  = (const float*)d_in[12];
    const float* ln2_g   = (const float*)d_in[13];
    const float* ln2_b   = (const float*)d_in[14];
    const float* fc1_w   = (const float*)d_in[15];
    const float* fc1_b   = (const float*)d_in[16];
    const float* fc2_w   = (const float*)d_in[17];
    const float* fc2_b   = (const float*)d_in[18];
    float* out = (float*)d_out;

    bf16 *p_xw, *p_qkv, *p_ctx, *p_ln2, *p_y1;
    bf16 *p_wqkv, *p_wp, *p_w1, *p_w2, *p_bias;
    float *p_h, *p_bqkv;
    cudaGetSymbolAddress((void**)&p_xw,   g_xw);
    cudaGetSymbolAddress((void**)&p_qkv,  g_qkv);
    cudaGetSymbolAddress((void**)&p_ctx,  g_ctx);
    cudaGetSymbolAddress((void**)&p_h,    g_h);
    cudaGetSymbolAddress((void**)&p_ln2,  g_ln2);
    cudaGetSymbolAddress((void**)&p_y1,   g_y1);
    cudaGetSymbolAddress((void**)&p_wqkv, g_wqkv);
    cudaGetSymbolAddress((void**)&p_bqkv, g_bqkv);
    cudaGetSymbolAddress((void**)&p_wp,   g_wp);
    cudaGetSymbolAddress((void**)&p_w1,   g_w1);
    cudaGetSymbolAddress((void**)&p_w2,   g_w2);
    cudaGetSymbolAddress((void**)&p_bias, g_bias);

    // weight packing / conversion + bias tiles
    const int WSMALL = CDIM * CDIM / 4, WBIG = CDIM * FFNDIM / 4;
    pack_qkv_kernel<<<(QKV_W4 + QKVN / 4 + 255) / 256, 256>>>(
        q_w, k_w, v_w, q_b, k_b, v_b, p_wqkv, p_bqkv);
    f2bf_kernel<<<(WSMALL + 255) / 256, 256>>>(proj_w, p_wp, WSMALL);
    f2bf_kernel<<<(WBIG   + 255) / 256, 256>>>(fc1_w,  p_w1, WBIG);
    f2bf_kernel<<<(WBIG   + 255) / 256, 256>>>(fc2_w,  p_w2, WBIG);
    bias_kernel<<<dim3(4, NHEADS), 256>>>(rpb, rpi, p_bias);

    // 1) LN1 + shift-roll + window partition (gather)
    ln_kernel<<<MTOK, 128>>>(hidden, ln1_g, ln1_b, p_xw, 1);

    // 2) fused QKV projection
    mma_gemm<0, bf16><<<dim3(QKVN / GBN, MTOK / GBM), 256>>>(
        p_xw, p_wqkv, p_bqkv, nullptr, p_qkv, MTOK, QKVN, CDIM);

    // 3) windowed attention (tensor cores)
    attn_mma_kernel<<<TOTWIN, 256>>>(p_qkv, p_bias, p_ctx);

    // 4) output projection + window-reverse + roll-back + residual (scatter)
    mma_gemm<2, float><<<dim3(CDIM / GBN, MTOK / GBM), 256>>>(
        p_ctx, p_wp, proj_b, hidden, p_h, MTOK, CDIM, CDIM);

    // 5) LN2
    ln_kernel<<<MTOK, 128>>>(p_h, ln2_g, ln2_b, p_ln2, 0);

    // 6) fc1 + exact GELU
    mma_gemm<1, bf16><<<dim3(FFNDIM / GBN, MTOK / GBM), 256>>>(
        p_ln2, p_w1, fc1_b, nullptr, p_y1, MTOK, FFNDIM, CDIM);

    // 7) fc2 + residual -> final output
    mma_gemm<3, float><<<dim3(CDIM / GBN, MTOK / GBM), 256>>>(
        p_y1, p_w2, fc2_b, p_h, out, MTOK, CDIM, FFNDIM);
}